// round 15
// baseline (speedup 1.0000x reference)
#include <cuda_runtime.h>

// ShiftWindowMSA fused kernel for GB300 (sm_103a) — round 14:
// R13 base + QK^T/softmax fusion: shuffle-based row max/sum inside the QK
// phase, unnormalized exp stored once, normalization deferred to AV stores.
// Softmax phase (barrier + smem round-trip + serial expf pass) deleted.

#define NTOK    49
#define CH      96
#define NH      3
#define HD      32
#define RS      100         // activation row stride (16B-aligned rows)
#define KWS     202         // KV weight tile row stride (cc-major [32][192+10])
#define QWS     106         // Q/proj weight tile row stride (cc-major [32][96+10])
#define ATS     52          // attn row stride
#define HP      224
#define THREADS 256

#define KVB     (32 * KWS)  // 6464 floats: one KV weight chunk buffer
#define QB      (32 * QWS)  // 3392 floats: one Q/proj weight chunk buffer

// smem float offsets
#define OA 0                // X -> K -> AV result       (49*100 = 4900)
#define OB 4900             // SX -> Q                   (4900)
#define OC 9800             // V                         (4900)
#define OD 14700            // weight ping-pong buffers (2*6464) / attn (3*49*52)
#define OINV (OD + 8100)    // 147 floats: 1/rowsum, in dead space after attn
#define OE 27628            // rel-pos bias table        (507)
#define SMEM_FLOATS 28135
#define SMEM_BYTES  (SMEM_FLOATS * 4)

typedef unsigned long long u64;

__device__ __forceinline__ u64 pk2(float lo, float hi) {
    u64 r; asm("mov.b64 %0, {%1, %2};" : "=l"(r) : "f"(lo), "f"(hi)); return r;
}
__device__ __forceinline__ void upk2(u64 v, float& lo, float& hi) {
    asm("mov.b64 {%0, %1}, %2;" : "=f"(lo), "=f"(hi) : "l"(v));
}
__device__ __forceinline__ void ffma2(u64& d, u64 a, u64 b) {
    asm("fma.rn.f32x2 %0, %1, %2, %0;" : "+l"(d) : "l"(a), "l"(b));
}

__global__ __launch_bounds__(THREADS, 2)
void swin_msa_kernel(const float* __restrict__ query,
                     const float* __restrict__ skipq,
                     const float* __restrict__ qkv_w,
                     const float* __restrict__ qkv_b,
                     const float* __restrict__ skip_w,
                     const float* __restrict__ skip_b,
                     const float* __restrict__ proj_w,
                     const float* __restrict__ proj_b,
                     const float* __restrict__ btab,
                     float* __restrict__ out)
{
    extern __shared__ float sm[];
    __shared__ int fval[NTOK];
    __shared__ int regid[NTOK];
    __shared__ int rowoff[NTOK];

    const int t   = threadIdx.x;
    const int blk = blockIdx.x;
    const int b   = blk >> 10;
    const int wi  = blk & 1023;
    const int wr  = wi >> 5;
    const int wc  = wi & 31;

    if (t < NTOK) {
        int r = t / 7, c = t - r * 7;
        fval[t] = 13 * r + c;
        int hg = wr * 7 + r;
        int wg = wc * 7 + c;
        int rh = (hg < 217) ? 0 : ((hg < 221) ? 1 : 2);
        int rw = (wg < 217) ? 0 : ((wg < 221) ? 1 : 2);
        regid[t] = rh * 3 + rw;
        int hs = hg + 3; if (hs >= HP) hs -= HP;
        int ws = wg + 3; if (ws >= HP) ws -= HP;
        rowoff[t] = (b * (HP * HP) + hs * HP + ws) * CH;
    }
    for (int i = t; i < 507; i += THREADS) sm[OE + i] = btab[i];
    __syncthreads();

    // ---- load x -> A, sx -> B ; prestage KV weight chunk 0 -> OD buf0 ----
    {
        const int warp = t >> 5, lane = t & 31;
        for (int n = warp; n < NTOK; n += 8) {
            if (lane < 24) {
                const int base = rowoff[n];
                float4 xv = *(const float4*)(query + base + lane * 4);
                float4 sv = *(const float4*)(skipq + base + lane * 4);
                *(float4*)&sm[OA + n * RS + lane * 4] = xv;
                *(float4*)&sm[OB + n * RS + lane * 4] = sv;
            }
        }
        for (int i2 = t; i2 < 192 * 32; i2 += THREADS) {
            const int j = i2 >> 5, cc = i2 & 31;
            sm[OD + cc * KWS + j] = qkv_w[j * CH + cc];
        }
    }
    __syncthreads();

    const int tj = t & 31;
    const int tn = t >> 5;

    // ================= KV GEMM: 49x192, tile 7 rows x 3 col-pairs ==============
    {
        u64 acc2[7][3];
        #pragma unroll
        for (int g = 0; g < 3; ++g) {
            const int col = 2 * tj + 64 * g;
            u64 b2 = pk2(qkv_b[col], qkv_b[col + 1]);
            #pragma unroll
            for (int i = 0; i < 7; ++i) acc2[i][g] = b2;
        }
        for (int ch = 0; ch < 3; ++ch) {
            if (ch < 2) {
                const int nb = OD + ((ch + 1) & 1) * KVB;
                for (int i2 = t; i2 < 192 * 32; i2 += THREADS) {
                    const int j = i2 >> 5, cc = i2 & 31;
                    sm[nb + cc * KWS + j] = qkv_w[j * CH + (ch + 1) * 32 + cc];
                }
            }
            const int cb = OD + (ch & 1) * KVB;
            #pragma unroll 2
            for (int cq = 0; cq < 8; ++cq) {
                float4 a4[7];
                #pragma unroll
                for (int i = 0; i < 7; ++i)
                    a4[i] = *(const float4*)&sm[OA + (tn + 8 * i) * RS + ch * 32 + cq * 4];
                const float* wb = sm + cb + (cq * 4) * KWS + 2 * tj;
                #pragma unroll
                for (int q = 0; q < 4; ++q) {
                    u64 w0 = *(const u64*)(wb + q * KWS);
                    u64 w1 = *(const u64*)(wb + q * KWS + 64);
                    u64 w2 = *(const u64*)(wb + q * KWS + 128);
                    #pragma unroll
                    for (int i = 0; i < 7; ++i) {
                        const float av = (q == 0) ? a4[i].x : (q == 1) ? a4[i].y
                                       : (q == 2) ? a4[i].z : a4[i].w;
                        const u64 a2 = pk2(av, av);
                        ffma2(acc2[i][0], a2, w0);
                        ffma2(acc2[i][1], a2, w1);
                        ffma2(acc2[i][2], a2, w2);
                    }
                }
            }
            __syncthreads();
        }
        #pragma unroll
        for (int i = 0; i < 7; ++i) {
            const int n = tn + 8 * i;
            if (n < NTOK) {
                #pragma unroll
                for (int g = 0; g < 3; ++g) {
                    const int col = 2 * tj + 64 * g;
                    float lo, hi; upk2(acc2[i][g], lo, hi);
                    if (col < 96) *(float2*)&sm[OA + n * RS + col] = make_float2(lo, hi);
                    else          *(float2*)&sm[OC + n * RS + col - 96] = make_float2(lo, hi);
                }
            }
        }
    }

    // ---- prestage Q weight chunk 0 -> OD buf0 ----
    for (int i2 = t; i2 < 96 * 32; i2 += THREADS) {
        const int j = i2 >> 5, cc = i2 & 31;
        sm[OD + cc * QWS + j] = skip_w[j * CH + cc];
    }
    __syncthreads();

    // ================= Q GEMM: 49x96, cols {2tj,2tj+1} pair + {64+tj} ==========
    {
        u64 accp[7]; float accs[7];
        {
            u64 b2 = pk2(skip_b[2 * tj], skip_b[2 * tj + 1]);
            const float bs = skip_b[64 + tj];
            #pragma unroll
            for (int i = 0; i < 7; ++i) { accp[i] = b2; accs[i] = bs; }
        }
        for (int ch = 0; ch < 3; ++ch) {
            if (ch < 2) {
                const int nb = OD + ((ch + 1) & 1) * QB;
                for (int i2 = t; i2 < 96 * 32; i2 += THREADS) {
                    const int j = i2 >> 5, cc = i2 & 31;
                    sm[nb + cc * QWS + j] = skip_w[j * CH + (ch + 1) * 32 + cc];
                }
            }
            const int cb = OD + (ch & 1) * QB;
            #pragma unroll 2
            for (int cq = 0; cq < 8; ++cq) {
                float4 a4[7];
                #pragma unroll
                for (int i = 0; i < 7; ++i)
                    a4[i] = *(const float4*)&sm[OB + (tn + 8 * i) * RS + ch * 32 + cq * 4];
                const float* wb = sm + cb + (cq * 4) * QWS;
                #pragma unroll
                for (int q = 0; q < 4; ++q) {
                    u64 w2 = *(const u64*)(wb + q * QWS + 2 * tj);
                    float ws = wb[q * QWS + 64 + tj];
                    #pragma unroll
                    for (int i = 0; i < 7; ++i) {
                        const float av = (q == 0) ? a4[i].x : (q == 1) ? a4[i].y
                                       : (q == 2) ? a4[i].z : a4[i].w;
                        ffma2(accp[i], pk2(av, av), w2);
                        accs[i] += av * ws;
                    }
                }
            }
            __syncthreads();
        }
        #pragma unroll
        for (int i = 0; i < 7; ++i) {
            const int n = tn + 8 * i;
            if (n < NTOK) {
                float lo, hi; upk2(accp[i], lo, hi);
                *(float2*)&sm[OB + n * RS + 2 * tj] = make_float2(lo, hi);
                sm[OB + n * RS + 64 + tj] = accs[i];
            }
        }
    }
    __syncthreads();

    // ================= QK^T + bias + mask + SOFTMAX (fused, in registers) ======
    // t = h*64 + rn*8 + rm ; 6 fully-converged warps; 8-lane group = (h, rn),
    // lanes rm=0..7 (rm=7 dummy). Row n = rn+7i; thread holds m = rm+7j.
    const float scale = 0.17677669529663687f;
    if (t < 192) {
        const int h    = t >> 6;
        const int rem  = t & 63;
        const int rn   = rem >> 3;              // 0..7 (7 = dummy group)
        const int rm   = rem & 7;               // 0..7 (7 = dummy lane)
        const bool valid = (rn < 7) && (rm < 7);
        float s[7][7];
        #pragma unroll
        for (int i = 0; i < 7; ++i)
            #pragma unroll
            for (int j = 0; j < 7; ++j) s[i][j] = 0.f;
        // dummy rn/rm=7 read rows 7..49 — in-bounds junk, results discarded
        const float* qb = sm + OB + rn * RS + h * HD;
        const float* kb = sm + OA + rm * RS + h * HD;
        #pragma unroll
        for (int kq = 0; kq < 8; ++kq) {
            float4 k4[7];
            #pragma unroll
            for (int j = 0; j < 7; ++j) k4[j] = *(const float4*)(kb + j * 7 * RS + kq * 4);
            #pragma unroll
            for (int i = 0; i < 7; ++i) {
                float4 q4 = *(const float4*)(qb + i * 7 * RS + kq * 4);
                #pragma unroll
                for (int j = 0; j < 7; ++j)
                    s[i][j] += q4.x * k4[j].x + q4.y * k4[j].y + q4.z * k4[j].z + q4.w * k4[j].w;
            }
        }
        float mx[7];
        #pragma unroll
        for (int i = 0; i < 7; ++i) {
            mx[i] = -1e30f;
            #pragma unroll
            for (int j = 0; j < 7; ++j) {
                float v = -1e30f;
                if (valid) {
                    const int n = rn + 7 * i;
                    const int m = rm + 7 * j;
                    const float bias = sm[OE + (fval[n] + fval[48 - m]) * 3 + h];
                    const float mask = (regid[n] != regid[m]) ? -100.f : 0.f;
                    v = s[i][j] * scale + bias + mask;
                }
                s[i][j] = v;
                mx[i] = fmaxf(mx[i], v);
            }
        }
        // group max over 8 lanes (full-warp converged shuffles)
        #pragma unroll
        for (int msk = 1; msk < 8; msk <<= 1)
            #pragma unroll
            for (int i = 0; i < 7; ++i)
                mx[i] = fmaxf(mx[i], __shfl_xor_sync(0xffffffffu, mx[i], msk));
        float ps[7];
        #pragma unroll
        for (int i = 0; i < 7; ++i) {
            ps[i] = 0.f;
            #pragma unroll
            for (int j = 0; j < 7; ++j) {
                s[i][j] = __expf(s[i][j] - mx[i]);   // dummy lanes -> exp(-huge)=0
                ps[i] += s[i][j];
            }
        }
        #pragma unroll
        for (int msk = 1; msk < 8; msk <<= 1)
            #pragma unroll
            for (int i = 0; i < 7; ++i)
                ps[i] += __shfl_xor_sync(0xffffffffu, ps[i], msk);
        if (valid) {
            #pragma unroll
            for (int i = 0; i < 7; ++i) {
                const int n = rn + 7 * i;
                #pragma unroll
                for (int j = 0; j < 7; ++j)
                    sm[OD + h * (NTOK * ATS) + n * ATS + (rm + 7 * j)] = s[i][j];
            }
            if (rm == 0) {
                #pragma unroll
                for (int i = 0; i < 7; ++i)
                    sm[OINV + h * NTOK + rn + 7 * i] = 1.f / ps[i];
            }
        }
    }
    __syncthreads();

    // ================= AV: dual-accumulator f32x2 over m; x inv at store =======
    {
        u64 acc2[7][3];
        #pragma unroll
        for (int i = 0; i < 7; ++i)
            #pragma unroll
            for (int h = 0; h < 3; ++h) acc2[i][h] = pk2(0.f, 0.f);
        #pragma unroll 2
        for (int mq = 0; mq < 12; ++mq) {
            const int m0 = 4 * mq;
            u64 va[3], vb[3];
            #pragma unroll
            for (int h = 0; h < 3; ++h) {
                const int vc = h * HD + tj;
                va[h] = pk2(sm[OC + m0 * RS + vc],       sm[OC + (m0 + 1) * RS + vc]);
                vb[h] = pk2(sm[OC + (m0 + 2) * RS + vc], sm[OC + (m0 + 3) * RS + vc]);
            }
            #pragma unroll
            for (int i = 0; i < 7; ++i) {
                const int n = tn + 8 * i;
                #pragma unroll
                for (int h = 0; h < 3; ++h) {
                    float4 a4 = *(const float4*)&sm[OD + h * (NTOK * ATS) + n * ATS + m0];
                    ffma2(acc2[i][h], pk2(a4.x, a4.y), va[h]);
                    ffma2(acc2[i][h], pk2(a4.z, a4.w), vb[h]);
                }
            }
        }
        {   // tail m = 48
            float vt[3];
            #pragma unroll
            for (int h = 0; h < 3; ++h) vt[h] = sm[OC + 48 * RS + h * HD + tj];
            #pragma unroll
            for (int i = 0; i < 7; ++i) {
                const int n = tn + 8 * i;
                #pragma unroll
                for (int h = 0; h < 3; ++h) {
                    const float at = sm[OD + h * (NTOK * ATS) + n * ATS + 48];
                    ffma2(acc2[i][h], pk2(at, 0.f), pk2(vt[h], 0.f));
                }
            }
        }
        __syncthreads();   // attn + inv reads done -> OD free; OA free
        #pragma unroll
        for (int i = 0; i < 7; ++i) {
            const int n = tn + 8 * i;
            if (n < NTOK) {
                #pragma unroll
                for (int h = 0; h < 3; ++h) {
                    float lo, hi; upk2(acc2[i][h], lo, hi);
                    sm[OA + n * RS + h * HD + tj] = (lo + hi) * sm[OINV + h * NTOK + n];
                }
            }
        }
    }

    // ---- prestage proj weight chunk 0 -> OD buf0 (over dead attn) ----
    for (int i2 = t; i2 < 96 * 32; i2 += THREADS) {
        const int j = i2 >> 5, cc = i2 & 31;
        sm[OD + cc * QWS + j] = proj_w[j * CH + cc];
    }
    __syncthreads();

    // ================= proj GEMM (reads A, ping-pong tiles in OD, stores gmem) ==
    {
        u64 accp[7]; float accs[7];
        {
            u64 b2 = pk2(proj_b[2 * tj], proj_b[2 * tj + 1]);
            const float bs = proj_b[64 + tj];
            #pragma unroll
            for (int i = 0; i < 7; ++i) { accp[i] = b2; accs[i] = bs; }
        }
        for (int ch = 0; ch < 3; ++ch) {
            if (ch < 2) {
                const int nb = OD + ((ch + 1) & 1) * QB;
                for (int i2 = t; i2 < 96 * 32; i2 += THREADS) {
                    const int j = i2 >> 5, cc = i2 & 31;
                    sm[nb + cc * QWS + j] = proj_w[j * CH + (ch + 1) * 32 + cc];
                }
            }
            const int cb = OD + (ch & 1) * QB;
            #pragma unroll 2
            for (int cq = 0; cq < 8; ++cq) {
                float4 a4[7];
                #pragma unroll
                for (int i = 0; i < 7; ++i)
                    a4[i] = *(const float4*)&sm[OA + (tn + 8 * i) * RS + ch * 32 + cq * 4];
                const float* wb = sm + cb + (cq * 4) * QWS;
                #pragma unroll
                for (int q = 0; q < 4; ++q) {
                    u64 w2 = *(const u64*)(wb + q * QWS + 2 * tj);
                    float ws = wb[q * QWS + 64 + tj];
                    #pragma unroll
                    for (int i = 0; i < 7; ++i) {
                        const float av = (q == 0) ? a4[i].x : (q == 1) ? a4[i].y
                                       : (q == 2) ? a4[i].z : a4[i].w;
                        ffma2(accp[i], pk2(av, av), w2);
                        accs[i] += av * ws;
                    }
                }
            }
            if (ch < 2) __syncthreads();
        }
        #pragma unroll
        for (int i = 0; i < 7; ++i) {
            const int n = tn + 8 * i;
            if (n < NTOK) {
                float lo, hi; upk2(accp[i], lo, hi);
                *(float2*)(out + rowoff[n] + 2 * tj) = make_float2(lo, hi);
                out[rowoff[n] + 64 + tj] = accs[i];
            }
        }
    }
}

extern "C" void kernel_launch(void* const* d_in, const int* in_sizes, int n_in,
                              void* d_out, int out_size)
{
    (void)in_sizes; (void)n_in; (void)out_size;
    const float* query  = (const float*)d_in[0];
    const float* skipq  = (const float*)d_in[1];
    const float* qkv_w  = (const float*)d_in[2];
    const float* qkv_b  = (const float*)d_in[3];
    const float* skip_w = (const float*)d_in[4];
    const float* skip_b = (const float*)d_in[5];
    const float* proj_w = (const float*)d_in[6];
    const float* proj_b = (const float*)d_in[7];
    const float* btab   = (const float*)d_in[8];
    float* out = (float*)d_out;

    cudaFuncSetAttribute(swin_msa_kernel,
                         cudaFuncAttributeMaxDynamicSharedMemorySize, SMEM_BYTES);

    swin_msa_kernel<<<4 * 1024, THREADS, SMEM_BYTES>>>(
        query, skipq, qkv_w, qkv_b, skip_w, skip_b, proj_w, proj_b, btab, out);
}

// round 16
// speedup vs baseline: 1.1424x; 1.1424x over previous
#include <cuda_runtime.h>
#include <cstdint>

// ShiftWindowMSA fused kernel for GB300 (sm_103a) — round 16:
// R13 base, with the KV GEMM moved to tensor cores (mma.sync m16n8k8 tf32,
// fp32 accum, exact-fp32 bias at store). Q/QK/softmax/AV/proj unchanged.

#define NTOK    49
#define CH      96
#define NH      3
#define HD      32
#define RS      100         // activation row stride (16B-aligned rows)
#define WTS     36          // KV tf32 weight tile: wt[col][cc_local], 192x36
#define QWS     106         // Q/proj weight tile row stride (cc-major [32][96+10])
#define ATS     52          // attn row stride
#define HP      224
#define THREADS 256

#define QB      (32 * QWS)  // 3392 floats: one Q/proj weight chunk buffer

// smem float offsets
#define OA 0                // X(tf32) -> K -> AV result  (49*100 = 4900)
#define OB 4900             // SX -> Q                    (4900)
#define OC 9800             // V                          (4900)
#define OD 14700            // KV tf32 tile (192*36=6912) / Q-proj ping-pong / attn
#define OINV (OD + 8100)    // 147 floats: 1/rowsum
#define OE 27628            // rel-pos bias table         (507)
#define SMEM_FLOATS 28135
#define SMEM_BYTES  (SMEM_FLOATS * 4)

typedef unsigned long long u64;

__device__ __forceinline__ u64 pk2(float lo, float hi) {
    u64 r; asm("mov.b64 %0, {%1, %2};" : "=l"(r) : "f"(lo), "f"(hi)); return r;
}
__device__ __forceinline__ void upk2(u64 v, float& lo, float& hi) {
    asm("mov.b64 {%0, %1}, %2;" : "=f"(lo), "=f"(hi) : "l"(v));
}
__device__ __forceinline__ void ffma2(u64& d, u64 a, u64 b) {
    asm("fma.rn.f32x2 %0, %1, %2, %0;" : "+l"(d) : "l"(a), "l"(b));
}
__device__ __forceinline__ float tf32r(float f) {
    uint32_t r; asm("cvt.rna.tf32.f32 %0, %1;" : "=r"(r) : "f"(f));
    return __uint_as_float(r);
}
__device__ __forceinline__ void mma_tf32(float& d0, float& d1, float& d2, float& d3,
                                         uint32_t a0, uint32_t a1, uint32_t a2, uint32_t a3,
                                         uint32_t b0, uint32_t b1) {
    asm volatile(
        "mma.sync.aligned.m16n8k8.row.col.f32.tf32.tf32.f32 "
        "{%0,%1,%2,%3}, {%4,%5,%6,%7}, {%8,%9}, {%0,%1,%2,%3};"
        : "+f"(d0), "+f"(d1), "+f"(d2), "+f"(d3)
        : "r"(a0), "r"(a1), "r"(a2), "r"(a3), "r"(b0), "r"(b1));
}

__global__ __launch_bounds__(THREADS, 2)
void swin_msa_kernel(const float* __restrict__ query,
                     const float* __restrict__ skipq,
                     const float* __restrict__ qkv_w,
                     const float* __restrict__ qkv_b,
                     const float* __restrict__ skip_w,
                     const float* __restrict__ skip_b,
                     const float* __restrict__ proj_w,
                     const float* __restrict__ proj_b,
                     const float* __restrict__ btab,
                     float* __restrict__ out)
{
    extern __shared__ float sm[];
    __shared__ int fval[NTOK];
    __shared__ int regid[NTOK];
    __shared__ int rowoff[NTOK];

    const int t   = threadIdx.x;
    const int blk = blockIdx.x;
    const int b   = blk >> 10;
    const int wi  = blk & 1023;
    const int wr  = wi >> 5;
    const int wc  = wi & 31;

    if (t < NTOK) {
        int r = t / 7, c = t - r * 7;
        fval[t] = 13 * r + c;
        int hg = wr * 7 + r;
        int wg = wc * 7 + c;
        int rh = (hg < 217) ? 0 : ((hg < 221) ? 1 : 2);
        int rw = (wg < 217) ? 0 : ((wg < 221) ? 1 : 2);
        regid[t] = rh * 3 + rw;
        int hs = hg + 3; if (hs >= HP) hs -= HP;
        int ws = wg + 3; if (ws >= HP) ws -= HP;
        rowoff[t] = (b * (HP * HP) + hs * HP + ws) * CH;
    }
    for (int i = t; i < 507; i += THREADS) sm[OE + i] = btab[i];
    __syncthreads();

    // ---- load x (tf32-rounded) -> A, sx -> B ; stage KV tf32 tile chunk 0 ----
    {
        const int warp = t >> 5, lane = t & 31;
        for (int n = warp; n < NTOK; n += 8) {
            if (lane < 24) {
                const int base = rowoff[n];
                float4 xv = *(const float4*)(query + base + lane * 4);
                float4 sv = *(const float4*)(skipq + base + lane * 4);
                *(float4*)&sm[OA + n * RS + lane * 4] =
                    make_float4(tf32r(xv.x), tf32r(xv.y), tf32r(xv.z), tf32r(xv.w));
                *(float4*)&sm[OB + n * RS + lane * 4] = sv;
            }
        }
        for (int i2 = t; i2 < 192 * 32; i2 += THREADS) {
            const int col = i2 >> 5, cc = i2 & 31;
            sm[OD + col * WTS + cc] = tf32r(qkv_w[col * CH + cc]);
        }
    }
    __syncthreads();

    const int tj = t & 31;
    const int w  = t >> 5;      // warp id
    const int tn = t >> 5;

    // ============ KV GEMM via tensor cores: D[64pad x 192] = X[64 x 96] W^T ====
    // warp w owns N-tiles {3w, 3w+1, 3w+2}; all 4 M-tiles; k in 3 chunks of 32.
    {
        const int g   = tj >> 2;   // groupID
        const int tig = tj & 3;    // threadID_in_group
        float acc[4][3][4];
        #pragma unroll
        for (int j = 0; j < 3; ++j) {
            const int n0 = (3 * w + j) * 8;
            const float b0v = qkv_b[n0 + 2 * tig];
            const float b1v = qkv_b[n0 + 2 * tig + 1];
            #pragma unroll
            for (int mt = 0; mt < 4; ++mt) {
                acc[mt][j][0] = b0v; acc[mt][j][1] = b1v;
                acc[mt][j][2] = b0v; acc[mt][j][3] = b1v;
            }
        }
        for (int ch = 0; ch < 3; ++ch) {
            if (ch) {
                __syncthreads();   // all warps done reading previous chunk
                for (int i2 = t; i2 < 192 * 32; i2 += THREADS) {
                    const int col = i2 >> 5, cc = i2 & 31;
                    sm[OD + col * WTS + cc] = tf32r(qkv_w[col * CH + ch * 32 + cc]);
                }
                __syncthreads();
            }
            #pragma unroll
            for (int ks = 0; ks < 4; ++ks) {
                const int kk = ch * 32 + ks * 8 + tig;
                uint32_t af[4][4];
                #pragma unroll
                for (int mt = 0; mt < 4; ++mt) {
                    const int r0 = (mt * 16 + g) * RS;
                    const int r1 = (mt * 16 + g + 8) * RS;   // junk rows land in OB: safe
                    af[mt][0] = __float_as_uint(sm[OA + r0 + kk]);
                    af[mt][1] = __float_as_uint(sm[OA + r1 + kk]);
                    af[mt][2] = __float_as_uint(sm[OA + r0 + kk + 4]);
                    af[mt][3] = __float_as_uint(sm[OA + r1 + kk + 4]);
                }
                #pragma unroll
                for (int j = 0; j < 3; ++j) {
                    const int n0 = (3 * w + j) * 8;
                    const int wbase = OD + (n0 + g) * WTS + ks * 8 + tig;
                    const uint32_t b0 = __float_as_uint(sm[wbase]);
                    const uint32_t b1 = __float_as_uint(sm[wbase + 4]);
                    #pragma unroll
                    for (int mt = 0; mt < 4; ++mt)
                        mma_tf32(acc[mt][j][0], acc[mt][j][1], acc[mt][j][2], acc[mt][j][3],
                                 af[mt][0], af[mt][1], af[mt][2], af[mt][3], b0, b1);
                }
            }
        }
        __syncthreads();   // all A-reads of X done -> OA may be overwritten with K
        #pragma unroll
        for (int mt = 0; mt < 4; ++mt) {
            const int r0 = mt * 16 + g;
            const int r1 = r0 + 8;
            #pragma unroll
            for (int j = 0; j < 3; ++j) {
                const int col = (3 * w + j) * 8 + 2 * tig;
                const int dbase = (col < 96) ? OA : OC;
                const int c     = (col < 96) ? col : (col - 96);
                if (r0 < NTOK)
                    *(float2*)&sm[dbase + r0 * RS + c] = make_float2(acc[mt][j][0], acc[mt][j][1]);
                if (r1 < NTOK)
                    *(float2*)&sm[dbase + r1 * RS + c] = make_float2(acc[mt][j][2], acc[mt][j][3]);
            }
        }
    }

    // ---- prestage Q weight chunk 0 -> OD buf0 ----
    __syncthreads();
    for (int i2 = t; i2 < 96 * 32; i2 += THREADS) {
        const int j = i2 >> 5, cc = i2 & 31;
        sm[OD + cc * QWS + j] = skip_w[j * CH + cc];
    }
    __syncthreads();

    // ================= Q GEMM: 49x96, cols {2tj,2tj+1} pair + {64+tj} ==========
    {
        u64 accp[7]; float accs[7];
        {
            u64 b2 = pk2(skip_b[2 * tj], skip_b[2 * tj + 1]);
            const float bs = skip_b[64 + tj];
            #pragma unroll
            for (int i = 0; i < 7; ++i) { accp[i] = b2; accs[i] = bs; }
        }
        for (int ch = 0; ch < 3; ++ch) {
            if (ch < 2) {
                const int nb = OD + ((ch + 1) & 1) * QB;
                for (int i2 = t; i2 < 96 * 32; i2 += THREADS) {
                    const int j = i2 >> 5, cc = i2 & 31;
                    sm[nb + cc * QWS + j] = skip_w[j * CH + (ch + 1) * 32 + cc];
                }
            }
            const int cb = OD + (ch & 1) * QB;
            #pragma unroll 2
            for (int cq = 0; cq < 8; ++cq) {
                float4 a4[7];
                #pragma unroll
                for (int i = 0; i < 7; ++i)
                    a4[i] = *(const float4*)&sm[OB + (tn + 8 * i) * RS + ch * 32 + cq * 4];
                const float* wb = sm + cb + (cq * 4) * QWS;
                #pragma unroll
                for (int q = 0; q < 4; ++q) {
                    u64 w2 = *(const u64*)(wb + q * QWS + 2 * tj);
                    float ws = wb[q * QWS + 64 + tj];
                    #pragma unroll
                    for (int i = 0; i < 7; ++i) {
                        const float av = (q == 0) ? a4[i].x : (q == 1) ? a4[i].y
                                       : (q == 2) ? a4[i].z : a4[i].w;
                        ffma2(accp[i], pk2(av, av), w2);
                        accs[i] += av * ws;
                    }
                }
            }
            __syncthreads();
        }
        #pragma unroll
        for (int i = 0; i < 7; ++i) {
            const int n = tn + 8 * i;
            if (n < NTOK) {
                float lo, hi; upk2(accp[i], lo, hi);
                *(float2*)&sm[OB + n * RS + 2 * tj] = make_float2(lo, hi);
                sm[OB + n * RS + 64 + tj] = accs[i];
            }
        }
    }
    __syncthreads();

    // ================= QK^T + bias + mask -> attn (stride ATS) =================
    const float scale = 0.17677669529663687f;
    if (t < NH * NTOK) {
        const int h  = t / NTOK;
        const int r  = t - h * NTOK;
        const int rn = r / 7;
        const int rm = r - rn * 7;
        float s[7][7];
        #pragma unroll
        for (int i = 0; i < 7; ++i)
            #pragma unroll
            for (int j = 0; j < 7; ++j) s[i][j] = 0.f;
        const float* qb = sm + OB + rn * RS + h * HD;
        const float* kb = sm + OA + rm * RS + h * HD;
        #pragma unroll
        for (int kq = 0; kq < 8; ++kq) {
            float4 k4[7];
            #pragma unroll
            for (int j = 0; j < 7; ++j) k4[j] = *(const float4*)(kb + j * 7 * RS + kq * 4);
            #pragma unroll
            for (int i = 0; i < 7; ++i) {
                float4 q4 = *(const float4*)(qb + i * 7 * RS + kq * 4);
                #pragma unroll
                for (int j = 0; j < 7; ++j)
                    s[i][j] += q4.x * k4[j].x + q4.y * k4[j].y + q4.z * k4[j].z + q4.w * k4[j].w;
            }
        }
        #pragma unroll
        for (int i = 0; i < 7; ++i) {
            const int n = rn + 7 * i;
            #pragma unroll
            for (int j = 0; j < 7; ++j) {
                const int m = rm + 7 * j;
                const float bias = sm[OE + (fval[n] + fval[48 - m]) * 3 + h];
                const float mask = (regid[n] != regid[m]) ? -100.f : 0.f;
                sm[OD + h * (NTOK * ATS) + n * ATS + m] = s[i][j] * scale + bias + mask;
            }
        }
    }
    __syncthreads();

    // ================= softmax =================
    if (t < NH * NTOK) {
        float* row = sm + OD + (t / NTOK) * (NTOK * ATS) + (t % NTOK) * ATS;
        float rv[49];
        #pragma unroll
        for (int q = 0; q < 12; ++q) {
            float4 v = *(const float4*)(row + 4 * q);
            rv[4 * q] = v.x; rv[4 * q + 1] = v.y; rv[4 * q + 2] = v.z; rv[4 * q + 3] = v.w;
        }
        rv[48] = row[48];
        float mx = rv[0];
        #pragma unroll
        for (int i = 1; i < 49; ++i) mx = fmaxf(mx, rv[i]);
        float ssum = 0.f;
        #pragma unroll
        for (int i = 0; i < 49; ++i) { rv[i] = __expf(rv[i] - mx); ssum += rv[i]; }
        const float inv = 1.f / ssum;
        #pragma unroll
        for (int q = 0; q < 12; ++q)
            *(float4*)(row + 4 * q) = make_float4(rv[4*q] * inv, rv[4*q+1] * inv,
                                                 rv[4*q+2] * inv, rv[4*q+3] * inv);
        row[48] = rv[48] * inv;
    }
    __syncthreads();

    // ================= AV: dual-accumulator f32x2 over m =================
    {
        u64 acc2[7][3];
        #pragma unroll
        for (int i = 0; i < 7; ++i)
            #pragma unroll
            for (int h = 0; h < 3; ++h) acc2[i][h] = pk2(0.f, 0.f);
        #pragma unroll 2
        for (int mq = 0; mq < 12; ++mq) {
            const int m0 = 4 * mq;
            u64 va[3], vb[3];
            #pragma unroll
            for (int h = 0; h < 3; ++h) {
                const int vc = h * HD + tj;
                va[h] = pk2(sm[OC + m0 * RS + vc],       sm[OC + (m0 + 1) * RS + vc]);
                vb[h] = pk2(sm[OC + (m0 + 2) * RS + vc], sm[OC + (m0 + 3) * RS + vc]);
            }
            #pragma unroll
            for (int i = 0; i < 7; ++i) {
                const int n = tn + 8 * i;
                #pragma unroll
                for (int h = 0; h < 3; ++h) {
                    float4 a4 = *(const float4*)&sm[OD + h * (NTOK * ATS) + n * ATS + m0];
                    ffma2(acc2[i][h], pk2(a4.x, a4.y), va[h]);
                    ffma2(acc2[i][h], pk2(a4.z, a4.w), vb[h]);
                }
            }
        }
        {   // tail m = 48
            float vt[3];
            #pragma unroll
            for (int h = 0; h < 3; ++h) vt[h] = sm[OC + 48 * RS + h * HD + tj];
            #pragma unroll
            for (int i = 0; i < 7; ++i) {
                const int n = tn + 8 * i;
                #pragma unroll
                for (int h = 0; h < 3; ++h) {
                    const float at = sm[OD + h * (NTOK * ATS) + n * ATS + 48];
                    ffma2(acc2[i][h], pk2(at, 0.f), pk2(vt[h], 0.f));
                }
            }
        }
        __syncthreads();   // attn reads done -> OD free; OA free
        #pragma unroll
        for (int i = 0; i < 7; ++i) {
            const int n = tn + 8 * i;
            if (n < NTOK) {
                #pragma unroll
                for (int h = 0; h < 3; ++h) {
                    float lo, hi; upk2(acc2[i][h], lo, hi);
                    sm[OA + n * RS + h * HD + tj] = lo + hi;
                }
            }
        }
    }

    // ---- prestage proj weight chunk 0 -> OD buf0 (over dead attn) ----
    for (int i2 = t; i2 < 96 * 32; i2 += THREADS) {
        const int j = i2 >> 5, cc = i2 & 31;
        sm[OD + cc * QWS + j] = proj_w[j * CH + cc];
    }
    __syncthreads();

    // ================= proj GEMM (reads A, ping-pong tiles in OD, stores gmem) ==
    {
        u64 accp[7]; float accs[7];
        {
            u64 b2 = pk2(proj_b[2 * tj], proj_b[2 * tj + 1]);
            const float bs = proj_b[64 + tj];
            #pragma unroll
            for (int i = 0; i < 7; ++i) { accp[i] = b2; accs[i] = bs; }
        }
        for (int ch = 0; ch < 3; ++ch) {
            if (ch < 2) {
                const int nb = OD + ((ch + 1) & 1) * QB;
                for (int i2 = t; i2 < 96 * 32; i2 += THREADS) {
                    const int j = i2 >> 5, cc = i2 & 31;
                    sm[nb + cc * QWS + j] = proj_w[j * CH + (ch + 1) * 32 + cc];
                }
            }
            const int cb = OD + (ch & 1) * QB;
            #pragma unroll 2
            for (int cq = 0; cq < 8; ++cq) {
                float4 a4[7];
                #pragma unroll
                for (int i = 0; i < 7; ++i)
                    a4[i] = *(const float4*)&sm[OA + (tn + 8 * i) * RS + ch * 32 + cq * 4];
                const float* wb = sm + cb + (cq * 4) * QWS;
                #pragma unroll
                for (int q = 0; q < 4; ++q) {
                    u64 w2 = *(const u64*)(wb + q * QWS + 2 * tj);
                    float ws = wb[q * QWS + 64 + tj];
                    #pragma unroll
                    for (int i = 0; i < 7; ++i) {
                        const float av = (q == 0) ? a4[i].x : (q == 1) ? a4[i].y
                                       : (q == 2) ? a4[i].z : a4[i].w;
                        ffma2(accp[i], pk2(av, av), w2);
                        accs[i] += av * ws;
                    }
                }
            }
            if (ch < 2) __syncthreads();
        }
        #pragma unroll
        for (int i = 0; i < 7; ++i) {
            const int n = tn + 8 * i;
            if (n < NTOK) {
                float lo, hi; upk2(accp[i], lo, hi);
                *(float2*)(out + rowoff[n] + 2 * tj) = make_float2(lo, hi);
                out[rowoff[n] + 64 + tj] = accs[i];
            }
        }
    }
}

extern "C" void kernel_launch(void* const* d_in, const int* in_sizes, int n_in,
                              void* d_out, int out_size)
{
    (void)in_sizes; (void)n_in; (void)out_size;
    const float* query  = (const float*)d_in[0];
    const float* skipq  = (const float*)d_in[1];
    const float* qkv_w  = (const float*)d_in[2];
    const float* qkv_b  = (const float*)d_in[3];
    const float* skip_w = (const float*)d_in[4];
    const float* skip_b = (const float*)d_in[5];
    const float* proj_w = (const float*)d_in[6];
    const float* proj_b = (const float*)d_in[7];
    const float* btab   = (const float*)d_in[8];
    float* out = (float*)d_out;

    cudaFuncSetAttribute(swin_msa_kernel,
                         cudaFuncAttributeMaxDynamicSharedMemorySize, SMEM_BYTES);

    swin_msa_kernel<<<4 * 1024, THREADS, SMEM_BYTES>>>(
        query, skipq, qkv_w, qkv_b, skip_w, skip_b, proj_w, proj_b, btab, out);
}

// round 17
// speedup vs baseline: 1.5360x; 1.3445x over previous
#include <cuda_runtime.h>
#include <cstdint>

// ShiftWindowMSA fused kernel for GB300 (sm_103a) — round 17:
// KV + Q + proj GEMMs all on tensor cores (mma.sync m16n8k8 tf32, fp32 accum,
// exact-fp32 bias). QK/softmax/AV remain exact fp32 FFMA2.

#define NTOK    49
#define CH      96
#define NH      3
#define HD      32
#define RS      100         // activation row stride (16B-aligned rows)
#define WTS     36          // KV tf32 weight tile: wt[col][cc_local], 192x36
#define WQS     100         // Q/proj tf32 weight tile: wt[col][k], 96x100
#define ATS     52          // attn row stride
#define HP      224
#define THREADS 256

// smem float offsets
#define OA 0                // X(tf32) -> K -> AV result  (49*100 = 4900)
#define OB 4900             // SX(tf32) -> Q              (4900)
#define OC 9800             // V                          (4900)
#define OD 14700            // KV chunk (6912) / Q wt (9600) / attn (7644) / proj wt (9600)
#define OE 27628            // rel-pos bias table         (507)
#define SMEM_FLOATS 28135
#define SMEM_BYTES  (SMEM_FLOATS * 4)

typedef unsigned long long u64;

__device__ __forceinline__ u64 pk2(float lo, float hi) {
    u64 r; asm("mov.b64 %0, {%1, %2};" : "=l"(r) : "f"(lo), "f"(hi)); return r;
}
__device__ __forceinline__ void upk2(u64 v, float& lo, float& hi) {
    asm("mov.b64 {%0, %1}, %2;" : "=f"(lo), "=f"(hi) : "l"(v));
}
__device__ __forceinline__ void ffma2(u64& d, u64 a, u64 b) {
    asm("fma.rn.f32x2 %0, %1, %2, %0;" : "+l"(d) : "l"(a), "l"(b));
}
__device__ __forceinline__ float tf32r(float f) {
    uint32_t r; asm("cvt.rna.tf32.f32 %0, %1;" : "=r"(r) : "f"(f));
    return __uint_as_float(r);
}
__device__ __forceinline__ void mma_tf32(float& d0, float& d1, float& d2, float& d3,
                                         uint32_t a0, uint32_t a1, uint32_t a2, uint32_t a3,
                                         uint32_t b0, uint32_t b1) {
    asm volatile(
        "mma.sync.aligned.m16n8k8.row.col.f32.tf32.tf32.f32 "
        "{%0,%1,%2,%3}, {%4,%5,%6,%7}, {%8,%9}, {%0,%1,%2,%3};"
        : "+f"(d0), "+f"(d1), "+f"(d2), "+f"(d3)
        : "r"(a0), "r"(a1), "r"(a2), "r"(a3), "r"(b0), "r"(b1));
}

__global__ __launch_bounds__(THREADS, 2)
void swin_msa_kernel(const float* __restrict__ query,
                     const float* __restrict__ skipq,
                     const float* __restrict__ qkv_w,
                     const float* __restrict__ qkv_b,
                     const float* __restrict__ skip_w,
                     const float* __restrict__ skip_b,
                     const float* __restrict__ proj_w,
                     const float* __restrict__ proj_b,
                     const float* __restrict__ btab,
                     float* __restrict__ out)
{
    extern __shared__ float sm[];
    __shared__ int fval[NTOK];
    __shared__ int regid[NTOK];
    __shared__ int rowoff[NTOK];

    const int t   = threadIdx.x;
    const int blk = blockIdx.x;
    const int b   = blk >> 10;
    const int wi  = blk & 1023;
    const int wr  = wi >> 5;
    const int wc  = wi & 31;

    if (t < NTOK) {
        int r = t / 7, c = t - r * 7;
        fval[t] = 13 * r + c;
        int hg = wr * 7 + r;
        int wg = wc * 7 + c;
        int rh = (hg < 217) ? 0 : ((hg < 221) ? 1 : 2);
        int rw = (wg < 217) ? 0 : ((wg < 221) ? 1 : 2);
        regid[t] = rh * 3 + rw;
        int hs = hg + 3; if (hs >= HP) hs -= HP;
        int ws = wg + 3; if (ws >= HP) ws -= HP;
        rowoff[t] = (b * (HP * HP) + hs * HP + ws) * CH;
    }
    for (int i = t; i < 507; i += THREADS) sm[OE + i] = btab[i];
    __syncthreads();

    // ---- load x, sx (tf32-rounded) ; stage KV tf32 weight chunk 0 ----
    {
        const int warp = t >> 5, lane = t & 31;
        for (int n = warp; n < NTOK; n += 8) {
            if (lane < 24) {
                const int base = rowoff[n];
                float4 xv = *(const float4*)(query + base + lane * 4);
                float4 sv = *(const float4*)(skipq + base + lane * 4);
                *(float4*)&sm[OA + n * RS + lane * 4] =
                    make_float4(tf32r(xv.x), tf32r(xv.y), tf32r(xv.z), tf32r(xv.w));
                *(float4*)&sm[OB + n * RS + lane * 4] =
                    make_float4(tf32r(sv.x), tf32r(sv.y), tf32r(sv.z), tf32r(sv.w));
            }
        }
        for (int i2 = t; i2 < 192 * 32; i2 += THREADS) {
            const int col = i2 >> 5, cc = i2 & 31;
            sm[OD + col * WTS + cc] = tf32r(qkv_w[col * CH + cc]);
        }
    }
    __syncthreads();

    const int tj  = t & 31;
    const int w   = t >> 5;     // warp id
    const int tn  = t >> 5;
    const int g   = tj >> 2;    // MMA groupID
    const int tig = tj & 3;     // MMA threadID_in_group

    // ============ KV GEMM (tensor): D[64pad x 192] = X[64 x 96] W^T ============
    {
        float acc[4][3][4];
        #pragma unroll
        for (int j = 0; j < 3; ++j) {
            const int n0 = (3 * w + j) * 8;
            const float b0v = qkv_b[n0 + 2 * tig];
            const float b1v = qkv_b[n0 + 2 * tig + 1];
            #pragma unroll
            for (int mt = 0; mt < 4; ++mt) {
                acc[mt][j][0] = b0v; acc[mt][j][1] = b1v;
                acc[mt][j][2] = b0v; acc[mt][j][3] = b1v;
            }
        }
        for (int ch = 0; ch < 3; ++ch) {
            if (ch) {
                __syncthreads();
                for (int i2 = t; i2 < 192 * 32; i2 += THREADS) {
                    const int col = i2 >> 5, cc = i2 & 31;
                    sm[OD + col * WTS + cc] = tf32r(qkv_w[col * CH + ch * 32 + cc]);
                }
                __syncthreads();
            }
            #pragma unroll
            for (int ks = 0; ks < 4; ++ks) {
                const int kk = ch * 32 + ks * 8 + tig;
                uint32_t af[4][4];
                #pragma unroll
                for (int mt = 0; mt < 4; ++mt) {
                    const int r0 = (mt * 16 + g) * RS;
                    const int r1 = (mt * 16 + g + 8) * RS;   // junk rows land in OB/OC: safe
                    af[mt][0] = __float_as_uint(sm[OA + r0 + kk]);
                    af[mt][1] = __float_as_uint(sm[OA + r1 + kk]);
                    af[mt][2] = __float_as_uint(sm[OA + r0 + kk + 4]);
                    af[mt][3] = __float_as_uint(sm[OA + r1 + kk + 4]);
                }
                #pragma unroll
                for (int j = 0; j < 3; ++j) {
                    const int n0 = (3 * w + j) * 8;
                    const int wbase = OD + (n0 + g) * WTS + ks * 8 + tig;
                    const uint32_t b0 = __float_as_uint(sm[wbase]);
                    const uint32_t b1 = __float_as_uint(sm[wbase + 4]);
                    #pragma unroll
                    for (int mt = 0; mt < 4; ++mt)
                        mma_tf32(acc[mt][j][0], acc[mt][j][1], acc[mt][j][2], acc[mt][j][3],
                                 af[mt][0], af[mt][1], af[mt][2], af[mt][3], b0, b1);
                }
            }
        }
        __syncthreads();   // X reads done -> OA may become K
        #pragma unroll
        for (int mt = 0; mt < 4; ++mt) {
            const int r0 = mt * 16 + g;
            const int r1 = r0 + 8;
            #pragma unroll
            for (int j = 0; j < 3; ++j) {
                const int col = (3 * w + j) * 8 + 2 * tig;
                const int dbase = (col < 96) ? OA : OC;
                const int c     = (col < 96) ? col : (col - 96);
                if (r0 < NTOK)
                    *(float2*)&sm[dbase + r0 * RS + c] = make_float2(acc[mt][j][0], acc[mt][j][1]);
                if (r1 < NTOK)
                    *(float2*)&sm[dbase + r1 * RS + c] = make_float2(acc[mt][j][2], acc[mt][j][3]);
            }
        }
    }
    __syncthreads();

    // ---- stage full Q weight tile (96x96 tf32, stride WQS) into OD ----
    for (int base = 0; base < 96 * 96; base += THREADS) {
        const int i2 = base + t;
        const int n = i2 / 96, cc = i2 - n * 96;
        sm[OD + n * WQS + cc] = tf32r(skip_w[i2]);
    }
    __syncthreads();

    // ============ Q GEMM (tensor): Q[64pad x 96] = SX[64 x 96] Wq^T ============
    {
        const int mt  = w & 3;
        const int nb0 = (w < 4) ? 0 : 6;
        float acc[6][4];
        #pragma unroll
        for (int j = 0; j < 6; ++j) {
            const int c0 = (nb0 + j) * 8 + 2 * tig;
            acc[j][0] = skip_b[c0]; acc[j][1] = skip_b[c0 + 1];
            acc[j][2] = acc[j][0];  acc[j][3] = acc[j][1];
        }
        #pragma unroll
        for (int ks = 0; ks < 12; ++ks) {
            const int kk = ks * 8 + tig;
            const int r0 = (mt * 16 + g) * RS;
            const uint32_t a0 = __float_as_uint(sm[OB + r0 + kk]);
            const uint32_t a1 = __float_as_uint(sm[OB + r0 + 8 * RS + kk]);
            const uint32_t a2 = __float_as_uint(sm[OB + r0 + kk + 4]);
            const uint32_t a3 = __float_as_uint(sm[OB + r0 + 8 * RS + kk + 4]);
            #pragma unroll
            for (int j = 0; j < 6; ++j) {
                const int wb = OD + ((nb0 + j) * 8 + g) * WQS + kk;
                mma_tf32(acc[j][0], acc[j][1], acc[j][2], acc[j][3],
                         a0, a1, a2, a3,
                         __float_as_uint(sm[wb]), __float_as_uint(sm[wb + 4]));
            }
        }
        __syncthreads();   // all SX reads complete before overwriting OB with Q
        #pragma unroll
        for (int j = 0; j < 6; ++j) {
            const int c0 = (nb0 + j) * 8 + 2 * tig;
            const int r0 = mt * 16 + g, r1 = r0 + 8;
            if (r0 < NTOK) *(float2*)&sm[OB + r0 * RS + c0] = make_float2(acc[j][0], acc[j][1]);
            if (r1 < NTOK) *(float2*)&sm[OB + r1 * RS + c0] = make_float2(acc[j][2], acc[j][3]);
        }
    }
    __syncthreads();

    // ================= QK^T + bias + mask -> attn (stride ATS) =================
    const float scale = 0.17677669529663687f;
    if (t < NH * NTOK) {
        const int h  = t / NTOK;
        const int r  = t - h * NTOK;
        const int rn = r / 7;
        const int rm = r - rn * 7;
        float s[7][7];
        #pragma unroll
        for (int i = 0; i < 7; ++i)
            #pragma unroll
            for (int j = 0; j < 7; ++j) s[i][j] = 0.f;
        const float* qb = sm + OB + rn * RS + h * HD;
        const float* kb = sm + OA + rm * RS + h * HD;
        #pragma unroll
        for (int kq = 0; kq < 8; ++kq) {
            float4 k4[7];
            #pragma unroll
            for (int j = 0; j < 7; ++j) k4[j] = *(const float4*)(kb + j * 7 * RS + kq * 4);
            #pragma unroll
            for (int i = 0; i < 7; ++i) {
                float4 q4 = *(const float4*)(qb + i * 7 * RS + kq * 4);
                #pragma unroll
                for (int j = 0; j < 7; ++j)
                    s[i][j] += q4.x * k4[j].x + q4.y * k4[j].y + q4.z * k4[j].z + q4.w * k4[j].w;
            }
        }
        #pragma unroll
        for (int i = 0; i < 7; ++i) {
            const int n = rn + 7 * i;
            #pragma unroll
            for (int j = 0; j < 7; ++j) {
                const int m = rm + 7 * j;
                const float bias = sm[OE + (fval[n] + fval[48 - m]) * 3 + h];
                const float mask = (regid[n] != regid[m]) ? -100.f : 0.f;
                sm[OD + h * (NTOK * ATS) + n * ATS + m] = s[i][j] * scale + bias + mask;
            }
        }
    }
    __syncthreads();

    // ================= softmax =================
    if (t < NH * NTOK) {
        float* row = sm + OD + (t / NTOK) * (NTOK * ATS) + (t % NTOK) * ATS;
        float rv[49];
        #pragma unroll
        for (int q = 0; q < 12; ++q) {
            float4 v = *(const float4*)(row + 4 * q);
            rv[4 * q] = v.x; rv[4 * q + 1] = v.y; rv[4 * q + 2] = v.z; rv[4 * q + 3] = v.w;
        }
        rv[48] = row[48];
        float mx = rv[0];
        #pragma unroll
        for (int i = 1; i < 49; ++i) mx = fmaxf(mx, rv[i]);
        float ssum = 0.f;
        #pragma unroll
        for (int i = 0; i < 49; ++i) { rv[i] = __expf(rv[i] - mx); ssum += rv[i]; }
        const float inv = 1.f / ssum;
        #pragma unroll
        for (int q = 0; q < 12; ++q)
            *(float4*)(row + 4 * q) = make_float4(rv[4*q] * inv, rv[4*q+1] * inv,
                                                 rv[4*q+2] * inv, rv[4*q+3] * inv);
        row[48] = rv[48] * inv;
    }
    __syncthreads();

    // ================= AV: dual-accumulator f32x2 over m =================
    {
        u64 acc2[7][3];
        #pragma unroll
        for (int i = 0; i < 7; ++i)
            #pragma unroll
            for (int h = 0; h < 3; ++h) acc2[i][h] = pk2(0.f, 0.f);
        #pragma unroll 2
        for (int mq = 0; mq < 12; ++mq) {
            const int m0 = 4 * mq;
            u64 va[3], vb[3];
            #pragma unroll
            for (int h = 0; h < 3; ++h) {
                const int vc = h * HD + tj;
                va[h] = pk2(sm[OC + m0 * RS + vc],       sm[OC + (m0 + 1) * RS + vc]);
                vb[h] = pk2(sm[OC + (m0 + 2) * RS + vc], sm[OC + (m0 + 3) * RS + vc]);
            }
            #pragma unroll
            for (int i = 0; i < 7; ++i) {
                const int n = tn + 8 * i;
                #pragma unroll
                for (int h = 0; h < 3; ++h) {
                    float4 a4 = *(const float4*)&sm[OD + h * (NTOK * ATS) + n * ATS + m0];
                    ffma2(acc2[i][h], pk2(a4.x, a4.y), va[h]);
                    ffma2(acc2[i][h], pk2(a4.z, a4.w), vb[h]);
                }
            }
        }
        {   // tail m = 48
            float vt[3];
            #pragma unroll
            for (int h = 0; h < 3; ++h) vt[h] = sm[OC + 48 * RS + h * HD + tj];
            #pragma unroll
            for (int i = 0; i < 7; ++i) {
                const int n = tn + 8 * i;
                #pragma unroll
                for (int h = 0; h < 3; ++h) {
                    const float at = sm[OD + h * (NTOK * ATS) + n * ATS + 48];
                    ffma2(acc2[i][h], pk2(at, 0.f), pk2(vt[h], 0.f));
                }
            }
        }
        __syncthreads();   // attn reads done -> OD free; OA free
        #pragma unroll
        for (int i = 0; i < 7; ++i) {
            const int n = tn + 8 * i;
            if (n < NTOK) {
                #pragma unroll
                for (int h = 0; h < 3; ++h) {
                    float lo, hi; upk2(acc2[i][h], lo, hi);
                    sm[OA + n * RS + h * HD + tj] = lo + hi;
                }
            }
        }
    }

    // ---- stage full proj weight tile (96x96 tf32) into OD (over dead attn) ----
    for (int base = 0; base < 96 * 96; base += THREADS) {
        const int i2 = base + t;
        const int n = i2 / 96, cc = i2 - n * 96;
        sm[OD + n * WQS + cc] = tf32r(proj_w[i2]);
    }
    __syncthreads();

    // ============ proj GEMM (tensor): out[49 x 96] = AV[64pad x 96] Wp^T =======
    {
        const int mt  = w & 3;
        const int nb0 = (w < 4) ? 0 : 6;
        float acc[6][4];
        #pragma unroll
        for (int j = 0; j < 6; ++j) {
            const int c0 = (nb0 + j) * 8 + 2 * tig;
            acc[j][0] = proj_b[c0]; acc[j][1] = proj_b[c0 + 1];
            acc[j][2] = acc[j][0];  acc[j][3] = acc[j][1];
        }
        #pragma unroll
        for (int ks = 0; ks < 12; ++ks) {
            const int kk = ks * 8 + tig;
            const int r0 = (mt * 16 + g) * RS;
            const uint32_t a0 = __float_as_uint(sm[OA + r0 + kk]);          // AV (tf32 via HW trunc)
            const uint32_t a1 = __float_as_uint(sm[OA + r0 + 8 * RS + kk]); // junk rows -> OB: safe
            const uint32_t a2 = __float_as_uint(sm[OA + r0 + kk + 4]);
            const uint32_t a3 = __float_as_uint(sm[OA + r0 + 8 * RS + kk + 4]);
            #pragma unroll
            for (int j = 0; j < 6; ++j) {
                const int wb = OD + ((nb0 + j) * 8 + g) * WQS + kk;
                mma_tf32(acc[j][0], acc[j][1], acc[j][2], acc[j][3],
                         a0, a1, a2, a3,
                         __float_as_uint(sm[wb]), __float_as_uint(sm[wb + 4]));
            }
        }
        #pragma unroll
        for (int j = 0; j < 6; ++j) {
            const int c0 = (nb0 + j) * 8 + 2 * tig;
            const int r0 = mt * 16 + g, r1 = r0 + 8;
            if (r0 < NTOK) *(float2*)(out + rowoff[r0] + c0) = make_float2(acc[j][0], acc[j][1]);
            if (r1 < NTOK) *(float2*)(out + rowoff[r1] + c0) = make_float2(acc[j][2], acc[j][3]);
        }
    }
}

extern "C" void kernel_launch(void* const* d_in, const int* in_sizes, int n_in,
                              void* d_out, int out_size)
{
    (void)in_sizes; (void)n_in; (void)out_size;
    const float* query  = (const float*)d_in[0];
    const float* skipq  = (const float*)d_in[1];
    const float* qkv_w  = (const float*)d_in[2];
    const float* qkv_b  = (const float*)d_in[3];
    const float* skip_w = (const float*)d_in[4];
    const float* skip_b = (const float*)d_in[5];
    const float* proj_w = (const float*)d_in[6];
    const float* proj_b = (const float*)d_in[7];
    const float* btab   = (const float*)d_in[8];
    float* out = (float*)d_out;

    cudaFuncSetAttribute(swin_msa_kernel,
                         cudaFuncAttributeMaxDynamicSharedMemorySize, SMEM_BYTES);

    swin_msa_kernel<<<4 * 1024, THREADS, SMEM_BYTES>>>(
        query, skipq, qkv_w, qkv_b, skip_w, skip_b, proj_w, proj_b, btab, out);
}